// round 1
// baseline (speedup 1.0000x reference)
#include <cuda_runtime.h>

// LRN with all-ones cross-channel 5x5 filter:
//   s[b,h,w]  = sum_c x[b,c,h,w]^2
//   y         = 5x5 zero-padded box filter of s
//   out       = x * (2 + 1e-4*y)^(-0.75)
//
// Fused single kernel: one block per (batch, 32x32 spatial tile).
// Phase 1: stream 96 channels, accumulate channel-sum-of-squares on a
//          36x36 halo tile (registers -> smem).
// Phase 2: 5x5 box filter + fast pow in smem.
// Phase 3: re-read the x tile (hot in L2) and scale, float4-vectorized.

#define Bn 16
#define Cn 96
#define Hn 224
#define Wn 224
#define HWn (Hn * Wn)          // 50176
#define TILE 32
#define HALO 2
#define Sn (TILE + 2 * HALO)   // 36
#define NPOS (Sn * Sn)         // 1296
#define NTHREADS 256
#define K_PER ((NPOS + NTHREADS - 1) / NTHREADS)  // 6

__global__ __launch_bounds__(NTHREADS)
void lrn_fused_kernel(const float* __restrict__ x, float* __restrict__ out) {
    __shared__ float s_s[NPOS];          // channel-summed squares, 36x36 halo tile
    __shared__ float f_s[TILE * TILE];   // per-pixel scale factor

    const int tid = threadIdx.x;
    const int b  = blockIdx.z;
    const int h0 = blockIdx.y * TILE;
    const int w0 = blockIdx.x * TILE;
    const int img_base = b * Cn * HWn;   // fits in int32 (max 77M)

    // ---------------- Phase 1: s = sum_c x^2 on the 36x36 halo tile ----------
    float acc[K_PER];
    int   base[K_PER];
    bool  valid[K_PER];
#pragma unroll
    for (int k = 0; k < K_PER; k++) {
        const int p = tid + k * NTHREADS;
        acc[k] = 0.0f;
        if (p < NPOS) {
            const int i  = p / Sn;
            const int j  = p - i * Sn;
            const int gh = h0 - HALO + i;
            const int gw = w0 - HALO + j;
            valid[k] = ((unsigned)gh < (unsigned)Hn) && ((unsigned)gw < (unsigned)Wn);
            base[k]  = img_base + gh * Wn + gw;
        } else {
            valid[k] = false;
            base[k]  = img_base;
        }
    }

#pragma unroll 4
    for (int c = 0; c < Cn; c++) {
        const int coff = c * HWn;
#pragma unroll
        for (int k = 0; k < K_PER; k++) {
            if (valid[k]) {
                const float v = __ldg(x + base[k] + coff);
                acc[k] = fmaf(v, v, acc[k]);
            }
        }
    }

#pragma unroll
    for (int k = 0; k < K_PER; k++) {
        const int p = tid + k * NTHREADS;
        if (p < NPOS) s_s[p] = acc[k];
    }
    __syncthreads();

    // ---------------- Phase 2: 5x5 box filter + pow(-0.75) -------------------
#pragma unroll
    for (int q = tid; q < TILE * TILE; q += NTHREADS) {
        const int i = q / TILE;
        const int j = q - i * TILE;
        float sum = 0.0f;
#pragma unroll
        for (int di = 0; di < 5; di++) {
#pragma unroll
            for (int dj = 0; dj < 5; dj++) {
                sum += s_s[(i + di) * Sn + (j + dj)];
            }
        }
        const float bse = 2.0f + 1e-4f * sum;         // >= 2, safe for fast log
        f_s[q] = __powf(bse, -0.75f);                 // exp2(-0.75*log2(b)), ~1e-6 rel
    }
    __syncthreads();

    // ---------------- Phase 3: out = x * f, float4 vectorized ----------------
    // 256 threads: 32 rows x 8 float4-quads. All addresses 16B aligned.
    const int r  = tid >> 3;          // 0..31 row in tile
    const int q4 = (tid & 7) * 4;     // 0,4,...,28 column offset
    const float4 f4 = *(const float4*)&f_s[r * TILE + q4];

    const int off = img_base + (h0 + r) * Wn + (w0 + q4);
    const float4* __restrict__ xp = (const float4*)(x + off);
    float4*       __restrict__ op = (float4*)(out + off);
    const int stride4 = HWn / 4;      // 12544

#pragma unroll 4
    for (int c = 0; c < Cn; c++) {
        float4 v = xp[c * stride4];
        v.x *= f4.x;
        v.y *= f4.y;
        v.z *= f4.z;
        v.w *= f4.w;
        op[c * stride4] = v;
    }
}

extern "C" void kernel_launch(void* const* d_in, const int* in_sizes, int n_in,
                              void* d_out, int out_size) {
    const float* x = (const float*)d_in[0];
    float* out = (float*)d_out;
    dim3 grid(Wn / TILE, Hn / TILE, Bn);   // 7 x 7 x 16 = 784 blocks
    lrn_fused_kernel<<<grid, NTHREADS>>>(x, out);
}